// round 2
// baseline (speedup 1.0000x reference)
#include <cuda_runtime.h>

#define N_NODES 50000
#define N_EDGES 800000
#define IN_FEAT 256
#define DIM_H 64
#define DIM_OUT 64

// scratch (static device globals; no allocations allowed)
__device__ float g_h_src[N_NODES * DIM_H];   // 12.8 MB
__device__ float g_a_src[N_NODES];
__device__ float g_a_dst[N_NODES];
__device__ float g_denom[N_NODES];
__device__ float g_agg[N_NODES * DIM_H];     // 12.8 MB
__device__ float g_wa_src[IN_FEAT];
__device__ float g_wa_dst[IN_FEAT];
__device__ int   g_is64;

// ---------------------------------------------------------------------------
// detect edge_index dtype: int64 values all in [0, N_NODES) -> is64=1,
// else it's int32. (False positive prob with int32 data ~ (N/2^32)^256 ~ 0.)
__global__ void detect_kernel(const int* __restrict__ e32) {
    if (threadIdx.x != 0 || blockIdx.x != 0) return;
    const long long* e64 = (const long long*)e32;
    int ok64 = 1;
    for (int i = 0; i < 256; i++) {
        long long v = e64[i];
        if (v < 0 || v >= N_NODES) { ok64 = 0; break; }
    }
    g_is64 = ok64;
}

__device__ __forceinline__ int load_src(const int* e32, int i, int is64) {
    return is64 ? e32[2 * i] : e32[i];
}
__device__ __forceinline__ int load_dst(const int* e32, int i, int is64) {
    return is64 ? e32[2 * (N_EDGES + i)] : e32[N_EDGES + i];
}

// ---------------------------------------------------------------------------
// zero denom + agg
__global__ void init_kernel() {
    int i = blockIdx.x * blockDim.x + threadIdx.x;
    int stride = gridDim.x * blockDim.x;
    for (int j = i; j < N_NODES * DIM_H; j += stride) g_agg[j] = 0.f;
    for (int j = i; j < N_NODES; j += stride) g_denom[j] = 0.f;
}

// wa_src = W_src @ att_src, wa_dst = W_dst @ att_dst  (256-length vectors)
__global__ void wa_kernel(const float* __restrict__ Wsrc,
                          const float* __restrict__ Wdst,
                          const float* __restrict__ atts,
                          const float* __restrict__ attd) {
    int k = blockIdx.x * blockDim.x + threadIdx.x;
    if (k >= IN_FEAT) return;
    float s = 0.f, d = 0.f;
#pragma unroll
    for (int j = 0; j < DIM_H; j++) {
        s += Wsrc[k * DIM_H + j] * atts[j];
        d += Wdst[k * DIM_H + j] * attd[j];
    }
    g_wa_src[k] = s;
    g_wa_dst[k] = d;
}

// ---------------------------------------------------------------------------
// h_src = x @ W_src ; a_src = x @ wa_src ; a_dst = x @ wa_dst
// One thread per node: 64 fp32 accumulators, W chunk in smem (warp-uniform
// broadcast reads -> conflict-free).
__global__ __launch_bounds__(256) void proj_kernel(const float* __restrict__ x,
                                                   const float* __restrict__ Wsrc) {
    __shared__ float Ws[64 * 64];   // 16 KB chunk of W_src
    __shared__ float was[64], wad[64];

    int node = blockIdx.x * 256 + threadIdx.x;
    float acc[64];
#pragma unroll
    for (int j = 0; j < 64; j++) acc[j] = 0.f;
    float as = 0.f, ad = 0.f;

    const float4* xrow = (const float4*)(x + (size_t)node * IN_FEAT);

    for (int kc = 0; kc < IN_FEAT / 64; kc++) {
        __syncthreads();
        const float4* wsrc4 = (const float4*)(Wsrc + kc * 64 * 64);
        float4* ws4 = (float4*)Ws;
#pragma unroll
        for (int i = 0; i < 4; i++) ws4[threadIdx.x + i * 256] = wsrc4[threadIdx.x + i * 256];
        if (threadIdx.x < 64) {
            was[threadIdx.x] = g_wa_src[kc * 64 + threadIdx.x];
            wad[threadIdx.x] = g_wa_dst[kc * 64 + threadIdx.x];
        }
        __syncthreads();

        if (node < N_NODES) {
#pragma unroll
            for (int k4 = 0; k4 < 16; k4++) {
                float4 xq = xrow[kc * 16 + k4];
                float xv[4] = {xq.x, xq.y, xq.z, xq.w};
#pragma unroll
                for (int kk = 0; kk < 4; kk++) {
                    int k = k4 * 4 + kk;
                    float xvv = xv[kk];
                    as += xvv * was[k];
                    ad += xvv * wad[k];
                    const float4* wrow = (const float4*)&Ws[k * 64];
#pragma unroll
                    for (int j4 = 0; j4 < 16; j4++) {
                        float4 w = wrow[j4];
                        acc[j4 * 4 + 0] += xvv * w.x;
                        acc[j4 * 4 + 1] += xvv * w.y;
                        acc[j4 * 4 + 2] += xvv * w.z;
                        acc[j4 * 4 + 3] += xvv * w.w;
                    }
                }
            }
        }
    }

    if (node < N_NODES) {
        float4* hout = (float4*)(g_h_src + (size_t)node * DIM_H);
#pragma unroll
        for (int j4 = 0; j4 < 16; j4++) {
            float4 v = {acc[j4 * 4 + 0], acc[j4 * 4 + 1], acc[j4 * 4 + 2], acc[j4 * 4 + 3]};
            hout[j4] = v;
        }
        g_a_src[node] = as;
        g_a_dst[node] = ad;
    }
}

// ---------------------------------------------------------------------------
// denom[d] += exp(leaky_relu(a_src[s] + a_dst[d]))   (no max-subtraction: e is
// O(few), exp cannot overflow; mathematically identical to segment softmax)
__global__ void denom_kernel(const int* __restrict__ e32) {
    int i = blockIdx.x * blockDim.x + threadIdx.x;
    if (i >= N_EDGES) return;
    int is64 = g_is64;
    int s = load_src(e32, i, is64);
    int d = load_dst(e32, i, is64);
    float e = g_a_src[s] + g_a_dst[d];
    e = e > 0.f ? e : 0.2f * e;
    atomicAdd(&g_denom[d], __expf(e));
}

// agg[d,:] += alpha(e) * h_src[s,:]   — one warp per edge, 2 feats per lane
__global__ __launch_bounds__(256) void scatter_kernel(const int* __restrict__ e32) {
    int warp = (blockIdx.x * blockDim.x + threadIdx.x) >> 5;
    int lane = threadIdx.x & 31;
    if (warp >= N_EDGES) return;
    int is64 = g_is64;
    int s = load_src(e32, warp, is64);
    int d = load_dst(e32, warp, is64);
    float e = g_a_src[s] + g_a_dst[d];
    e = e > 0.f ? e : 0.2f * e;
    float alpha = __expf(e) / g_denom[d];
    float v0 = g_h_src[(size_t)s * 64 + lane] * alpha;
    float v1 = g_h_src[(size_t)s * 64 + 32 + lane] * alpha;
    atomicAdd(&g_agg[(size_t)d * 64 + lane], v0);
    atomicAdd(&g_agg[(size_t)d * 64 + 32 + lane], v1);
}

// ---------------------------------------------------------------------------
// out = relu(agg + bias_conv) @ W_lin + b_lin
__global__ __launch_bounds__(256) void out_kernel(const float* __restrict__ Wlin,
                                                  const float* __restrict__ bias_conv,
                                                  const float* __restrict__ blin,
                                                  float* __restrict__ out) {
    __shared__ float Ws[64 * 64];
    __shared__ float bconv[64], bl[64];

    float4* ws4 = (float4*)Ws;
    const float4* wl4 = (const float4*)Wlin;
#pragma unroll
    for (int i = 0; i < 4; i++) ws4[threadIdx.x + i * 256] = wl4[threadIdx.x + i * 256];
    if (threadIdx.x < 64) {
        bconv[threadIdx.x] = bias_conv[threadIdx.x];
        bl[threadIdx.x] = blin[threadIdx.x];
    }
    __syncthreads();

    int node = blockIdx.x * 256 + threadIdx.x;
    if (node >= N_NODES) return;

    float acc[64];
#pragma unroll
    for (int j = 0; j < 64; j++) acc[j] = bl[j];

    const float4* arow = (const float4*)(g_agg + (size_t)node * 64);
#pragma unroll
    for (int k4 = 0; k4 < 16; k4++) {
        float4 aq = arow[k4];
        float av[4] = {aq.x, aq.y, aq.z, aq.w};
#pragma unroll
        for (int kk = 0; kk < 4; kk++) {
            int k = k4 * 4 + kk;
            float h = av[kk] + bconv[k];
            h = h > 0.f ? h : 0.f;
            const float4* wrow = (const float4*)&Ws[k * 64];
#pragma unroll
            for (int j4 = 0; j4 < 16; j4++) {
                float4 w = wrow[j4];
                acc[j4 * 4 + 0] += h * w.x;
                acc[j4 * 4 + 1] += h * w.y;
                acc[j4 * 4 + 2] += h * w.z;
                acc[j4 * 4 + 3] += h * w.w;
            }
        }
    }

    float4* orow = (float4*)(out + (size_t)node * 64);
#pragma unroll
    for (int j4 = 0; j4 < 16; j4++) {
        float4 v = {acc[j4 * 4 + 0], acc[j4 * 4 + 1], acc[j4 * 4 + 2], acc[j4 * 4 + 3]};
        orow[j4] = v;
    }
}

// ---------------------------------------------------------------------------
extern "C" void kernel_launch(void* const* d_in, const int* in_sizes, int n_in,
                              void* d_out, int out_size) {
    const float* x     = (const float*)d_in[0];
    const int*   e32   = (const int*)d_in[1];
    const float* Wsrc  = (const float*)d_in[2];
    const float* Wdst  = (const float*)d_in[3];
    const float* atts  = (const float*)d_in[4];
    const float* attd  = (const float*)d_in[5];
    const float* bconv = (const float*)d_in[6];
    const float* Wlin  = (const float*)d_in[7];
    const float* blin  = (const float*)d_in[8];
    float*       out   = (float*)d_out;

    detect_kernel<<<1, 32>>>(e32);
    init_kernel<<<256, 256>>>();
    wa_kernel<<<1, 256>>>(Wsrc, Wdst, atts, attd);
    proj_kernel<<<(N_NODES + 255) / 256, 256>>>(x, Wsrc);
    denom_kernel<<<(N_EDGES + 255) / 256, 256>>>(e32);
    scatter_kernel<<<(int)(((long long)N_EDGES * 32 + 255) / 256), 256>>>(e32);
    out_kernel<<<(N_NODES + 255) / 256, 256>>>(Wlin, bconv, blin, out);
}

// round 3
// speedup vs baseline: 1.3264x; 1.3264x over previous
#include <cuda_runtime.h>

#define N_NODES 50000
#define N_EDGES 800000
#define IN_FEAT 256
#define DIM_H 64
#define DIM_OUT 64

// scratch (static device globals; no allocations allowed)
__device__ float g_h_src[N_NODES * DIM_H];   // 12.8 MB
__device__ float g_a_src[N_NODES];
__device__ float g_a_dst[N_NODES];
__device__ float g_denom[N_NODES];
__device__ float g_eexp[N_EDGES];            // exp(leaky_relu(e)) per edge
__device__ float g_agg[N_NODES * DIM_H];     // 12.8 MB
__device__ float g_wa_src[IN_FEAT];
__device__ float g_wa_dst[IN_FEAT];
__device__ int   g_is64;

// ---------------------------------------------------------------------------
// detect edge_index dtype: int64 values all in [0, N_NODES) -> is64=1,
// else int32. (False positive prob with int32 data ~ (N/2^32)^256 ~ 0.)
__global__ void detect_kernel(const int* __restrict__ e32) {
    if (threadIdx.x != 0 || blockIdx.x != 0) return;
    const long long* e64 = (const long long*)e32;
    int ok64 = 1;
    for (int i = 0; i < 256; i++) {
        long long v = e64[i];
        if (v < 0 || v >= N_NODES) { ok64 = 0; break; }
    }
    g_is64 = ok64;
}

__device__ __forceinline__ int load_src(const int* e32, int i, int is64) {
    return is64 ? e32[2 * i] : e32[i];
}
__device__ __forceinline__ int load_dst(const int* e32, int i, int is64) {
    return is64 ? e32[2 * (N_EDGES + i)] : e32[N_EDGES + i];
}

// ---------------------------------------------------------------------------
__global__ void init_kernel() {
    int i = blockIdx.x * blockDim.x + threadIdx.x;
    int stride = gridDim.x * blockDim.x;
    for (int j = i; j < N_NODES * DIM_H; j += stride) g_agg[j] = 0.f;
    for (int j = i; j < N_NODES; j += stride) g_denom[j] = 0.f;
}

// wa_src = W_src @ att_src, wa_dst = W_dst @ att_dst  (256-length vectors)
__global__ void wa_kernel(const float* __restrict__ Wsrc,
                          const float* __restrict__ Wdst,
                          const float* __restrict__ atts,
                          const float* __restrict__ attd) {
    int k = blockIdx.x * blockDim.x + threadIdx.x;
    if (k >= IN_FEAT) return;
    float s = 0.f, d = 0.f;
#pragma unroll
    for (int j = 0; j < DIM_H; j++) {
        s += Wsrc[k * DIM_H + j] * atts[j];
        d += Wdst[k * DIM_H + j] * attd[j];
    }
    g_wa_src[k] = s;
    g_wa_dst[k] = d;
}

// ---------------------------------------------------------------------------
// h_src = x @ W_src ; a_src = x @ wa_src ; a_dst = x @ wa_dst
// 128 threads/block, 64-node x 64-feat tile, 4x8 register tile per thread.
__global__ __launch_bounds__(128) void proj_kernel(const float* __restrict__ x,
                                                   const float* __restrict__ Wsrc) {
    __shared__ float Xs[32][68];                    // [k][node], padded
    __shared__ __align__(16) float Ws_s[32][64];    // [k][feat]
    __shared__ float was_s[32], wad_s[32];

    int tx = threadIdx.x;
    int node0 = blockIdx.x * 64;
    int fg = tx & 7;          // feat group: feats fg*8 .. fg*8+7
    int ng = tx >> 3;         // node group: nodes ng*4 .. ng*4+3

    float acc[4][8];
#pragma unroll
    for (int i = 0; i < 4; i++)
#pragma unroll
        for (int j = 0; j < 8; j++) acc[i][j] = 0.f;
    float as = 0.f, ad = 0.f;   // valid for tx < 64 (node node0+tx)

    for (int kc = 0; kc < IN_FEAT / 32; kc++) {
        __syncthreads();
        // stage X tile transposed: 64 nodes x 32 k  (512 float4 loads)
#pragma unroll
        for (int i = tx; i < 512; i += 128) {
            int nd = i >> 3, kq = i & 7;
            int row = node0 + nd; if (row >= N_NODES) row = N_NODES - 1;
            float4 v = ((const float4*)(x + (size_t)row * IN_FEAT + kc * 32))[kq];
            Xs[kq * 4 + 0][nd] = v.x;
            Xs[kq * 4 + 1][nd] = v.y;
            Xs[kq * 4 + 2][nd] = v.z;
            Xs[kq * 4 + 3][nd] = v.w;
        }
        // stage W chunk: 32 x 64 (512 float4)
        const float4* w4 = (const float4*)(Wsrc + kc * 32 * 64);
        float4* ws4 = (float4*)&Ws_s[0][0];
#pragma unroll
        for (int i = tx; i < 512; i += 128) ws4[i] = w4[i];
        if (tx < 32) was_s[tx] = g_wa_src[kc * 32 + tx];
        else if (tx < 64) wad_s[tx - 32] = g_wa_dst[kc * 32 + tx - 32];
        __syncthreads();

        // attention logits (first 64 threads, one node each)
        if (tx < 64) {
#pragma unroll
            for (int k = 0; k < 32; k++) {
                float xv = Xs[k][tx];
                as += xv * was_s[k];
                ad += xv * wad_s[k];
            }
        }

        // main 4x8 register-tiled GEMM
#pragma unroll
        for (int k = 0; k < 32; k++) {
            float xv[4];
#pragma unroll
            for (int i = 0; i < 4; i++) xv[i] = Xs[k][ng * 4 + i];
            float4 w0 = ((const float4*)&Ws_s[k][0])[fg * 2 + 0];
            float4 w1 = ((const float4*)&Ws_s[k][0])[fg * 2 + 1];
            float wv[8] = {w0.x, w0.y, w0.z, w0.w, w1.x, w1.y, w1.z, w1.w};
#pragma unroll
            for (int i = 0; i < 4; i++)
#pragma unroll
                for (int j = 0; j < 8; j++) acc[i][j] += xv[i] * wv[j];
        }
    }

    int nmax = N_NODES - node0;
#pragma unroll
    for (int i = 0; i < 4; i++) {
        int nd = ng * 4 + i;
        if (nd < nmax) {
            float4* o = (float4*)(g_h_src + (size_t)(node0 + nd) * DIM_H + fg * 8);
            float4 v0 = {acc[i][0], acc[i][1], acc[i][2], acc[i][3]};
            float4 v1 = {acc[i][4], acc[i][5], acc[i][6], acc[i][7]};
            o[0] = v0; o[1] = v1;
        }
    }
    if (tx < 64 && tx < nmax) {
        g_a_src[node0 + tx] = as;
        g_a_dst[node0 + tx] = ad;
    }
}

// ---------------------------------------------------------------------------
// eexp[i] = exp(leaky_relu(a_src[s] + a_dst[d]));  denom[d] += eexp[i]
// (no max-subtraction: e is O(few), exp cannot overflow)
__global__ void denom_kernel(const int* __restrict__ e32) {
    int i = blockIdx.x * blockDim.x + threadIdx.x;
    if (i >= N_EDGES) return;
    int is64 = g_is64;
    int s = load_src(e32, i, is64);
    int d = load_dst(e32, i, is64);
    float e = g_a_src[s] + g_a_dst[d];
    e = e > 0.f ? e : 0.2f * e;
    float ex = __expf(e);
    g_eexp[i] = ex;
    atomicAdd(&g_denom[d], ex);
}

// agg[d,:] += alpha * h_src[s,:]  — 16 threads/edge, red.v4.f32 (4 feats/thread)
__global__ __launch_bounds__(256) void scatter_kernel(const int* __restrict__ e32) {
    int t = blockIdx.x * blockDim.x + threadIdx.x;
    int edge = t >> 4;
    int q = t & 15;
    if (edge >= N_EDGES) return;
    int is64 = g_is64;
    int s = load_src(e32, edge, is64);
    int d = load_dst(e32, edge, is64);
    float alpha = g_eexp[edge] / g_denom[d];
    float4 v = *(const float4*)(g_h_src + (size_t)s * DIM_H + q * 4);
    v.x *= alpha; v.y *= alpha; v.z *= alpha; v.w *= alpha;
    float* p = g_agg + (size_t)d * DIM_H + q * 4;
    asm volatile("red.global.add.v4.f32 [%0], {%1, %2, %3, %4};"
                 :: "l"(p), "f"(v.x), "f"(v.y), "f"(v.z), "f"(v.w)
                 : "memory");
}

// ---------------------------------------------------------------------------
// out = relu(agg + bias_conv) @ W_lin + b_lin  — same 4x8 tiling, K=64
__global__ __launch_bounds__(128) void out_kernel(const float* __restrict__ Wlin,
                                                  const float* __restrict__ bias_conv,
                                                  const float* __restrict__ blin,
                                                  float* __restrict__ out) {
    __shared__ float Hs[32][68];
    __shared__ __align__(16) float Ws_s[32][64];
    __shared__ float bc_s[32], bl_s[64];

    int tx = threadIdx.x;
    int node0 = blockIdx.x * 64;
    int fg = tx & 7, ng = tx >> 3;

    if (tx < 64) bl_s[tx] = blin[tx];

    float acc[4][8];
#pragma unroll
    for (int i = 0; i < 4; i++)
#pragma unroll
        for (int j = 0; j < 8; j++) acc[i][j] = 0.f;

    for (int kc = 0; kc < DIM_H / 32; kc++) {
        __syncthreads();
        if (tx < 32) bc_s[tx] = bias_conv[kc * 32 + tx];
        __syncthreads();
#pragma unroll
        for (int i = tx; i < 512; i += 128) {
            int nd = i >> 3, kq = i & 7;
            int row = node0 + nd; if (row >= N_NODES) row = N_NODES - 1;
            float4 v = ((const float4*)(g_agg + (size_t)row * DIM_H + kc * 32))[kq];
            float b0 = bc_s[kq * 4 + 0], b1 = bc_s[kq * 4 + 1];
            float b2 = bc_s[kq * 4 + 2], b3 = bc_s[kq * 4 + 3];
            float h0 = v.x + b0, h1 = v.y + b1, h2 = v.z + b2, h3 = v.w + b3;
            Hs[kq * 4 + 0][nd] = h0 > 0.f ? h0 : 0.f;
            Hs[kq * 4 + 1][nd] = h1 > 0.f ? h1 : 0.f;
            Hs[kq * 4 + 2][nd] = h2 > 0.f ? h2 : 0.f;
            Hs[kq * 4 + 3][nd] = h3 > 0.f ? h3 : 0.f;
        }
        const float4* w4 = (const float4*)(Wlin + kc * 32 * 64);
        float4* ws4 = (float4*)&Ws_s[0][0];
#pragma unroll
        for (int i = tx; i < 512; i += 128) ws4[i] = w4[i];
        __syncthreads();

#pragma unroll
        for (int k = 0; k < 32; k++) {
            float hv[4];
#pragma unroll
            for (int i = 0; i < 4; i++) hv[i] = Hs[k][ng * 4 + i];
            float4 w0 = ((const float4*)&Ws_s[k][0])[fg * 2 + 0];
            float4 w1 = ((const float4*)&Ws_s[k][0])[fg * 2 + 1];
            float wv[8] = {w0.x, w0.y, w0.z, w0.w, w1.x, w1.y, w1.z, w1.w};
#pragma unroll
            for (int i = 0; i < 4; i++)
#pragma unroll
                for (int j = 0; j < 8; j++) acc[i][j] += hv[i] * wv[j];
        }
    }

    int nmax = N_NODES - node0;
#pragma unroll
    for (int i = 0; i < 4; i++) {
        int nd = ng * 4 + i;
        if (nd < nmax) {
            float4* o = (float4*)(out + (size_t)(node0 + nd) * DIM_OUT + fg * 8);
            float4 v0 = {acc[i][0] + bl_s[fg * 8 + 0], acc[i][1] + bl_s[fg * 8 + 1],
                         acc[i][2] + bl_s[fg * 8 + 2], acc[i][3] + bl_s[fg * 8 + 3]};
            float4 v1 = {acc[i][4] + bl_s[fg * 8 + 4], acc[i][5] + bl_s[fg * 8 + 5],
                         acc[i][6] + bl_s[fg * 8 + 6], acc[i][7] + bl_s[fg * 8 + 7]};
            o[0] = v0; o[1] = v1;
        }
    }
}

// ---------------------------------------------------------------------------
extern "C" void kernel_launch(void* const* d_in, const int* in_sizes, int n_in,
                              void* d_out, int out_size) {
    const float* x     = (const float*)d_in[0];
    const int*   e32   = (const int*)d_in[1];
    const float* Wsrc  = (const float*)d_in[2];
    const float* Wdst  = (const float*)d_in[3];
    const float* atts  = (const float*)d_in[4];
    const float* attd  = (const float*)d_in[5];
    const float* bconv = (const float*)d_in[6];
    const float* Wlin  = (const float*)d_in[7];
    const float* blin  = (const float*)d_in[8];
    float*       out   = (float*)d_out;

    const int NODE_BLOCKS = (N_NODES + 63) / 64;   // 782

    detect_kernel<<<1, 32>>>(e32);
    init_kernel<<<512, 256>>>();
    wa_kernel<<<1, 256>>>(Wsrc, Wdst, atts, attd);
    proj_kernel<<<NODE_BLOCKS, 128>>>(x, Wsrc);
    denom_kernel<<<(N_EDGES + 255) / 256, 256>>>(e32);
    scatter_kernel<<<(N_EDGES * 16) / 256, 256>>>(e32);
    out_kernel<<<NODE_BLOCKS, 128>>>(Wlin, bconv, blin, out);
}

// round 4
// speedup vs baseline: 1.5771x; 1.1890x over previous
#include <cuda_runtime.h>

#define N_NODES 50000
#define N_EDGES 800000
#define IN_FEAT 256
#define DIM_H 64
#define DIM_OUT 64

// scratch (static device globals; no allocations allowed)
__device__ float g_h_src[N_NODES * DIM_H];   // 12.8 MB
__device__ float g_a_src[N_NODES];
__device__ float g_a_dst[N_NODES];
__device__ float g_denom[N_NODES];
__device__ float g_eexp[N_EDGES];            // exp(e), then alpha in-place
__device__ float g_agg[N_NODES * DIM_H];     // 12.8 MB
__device__ float g_wa_src[IN_FEAT];
__device__ float g_wa_dst[IN_FEAT];
__device__ int   g_is64;

// ---------------------------------------------------------------------------
__global__ void detect_kernel(const int* __restrict__ e32) {
    if (threadIdx.x != 0 || blockIdx.x != 0) return;
    const long long* e64 = (const long long*)e32;
    int ok64 = 1;
    for (int i = 0; i < 256; i++) {
        long long v = e64[i];
        if (v < 0 || v >= N_NODES) { ok64 = 0; break; }
    }
    g_is64 = ok64;
}

__device__ __forceinline__ int load_src(const int* e32, int i, int is64) {
    return is64 ? e32[2 * i] : e32[i];
}
__device__ __forceinline__ int load_dst(const int* e32, int i, int is64) {
    return is64 ? e32[2 * (N_EDGES + i)] : e32[N_EDGES + i];
}

// ---------------------------------------------------------------------------
__global__ void init_kernel() {
    int i = blockIdx.x * blockDim.x + threadIdx.x;
    int stride = gridDim.x * blockDim.x;
    for (int j = i; j < N_NODES * DIM_H; j += stride) g_agg[j] = 0.f;
    for (int j = i; j < N_NODES; j += stride) g_denom[j] = 0.f;
}

// wa_src = W_src @ att_src, wa_dst = W_dst @ att_dst
__global__ void wa_kernel(const float* __restrict__ Wsrc,
                          const float* __restrict__ Wdst,
                          const float* __restrict__ atts,
                          const float* __restrict__ attd) {
    int k = blockIdx.x * blockDim.x + threadIdx.x;
    if (k >= IN_FEAT) return;
    float s = 0.f, d = 0.f;
#pragma unroll
    for (int j = 0; j < DIM_H; j++) {
        s += Wsrc[k * DIM_H + j] * atts[j];
        d += Wdst[k * DIM_H + j] * attd[j];
    }
    g_wa_src[k] = s;
    g_wa_dst[k] = d;
}

// ---------------------------------------------------------------------------
// h_src = x @ W_src ; a_src = x @ wa_src ; a_dst = x @ wa_dst
// 128 threads/block, 128-node x 64-feat tile, 8x8 register tile per thread.
__global__ __launch_bounds__(128) void proj_kernel(const float* __restrict__ x,
                                                   const float* __restrict__ Wsrc) {
    __shared__ __align__(16) float Xs[32][136];     // [k][node], 128 + pad 8
    __shared__ __align__(16) float Ws_s[32][64];    // [k][feat]
    __shared__ float was_s[32], wad_s[32];

    int tx = threadIdx.x;
    int node0 = blockIdx.x * 128;
    int fg = tx & 7;          // feats fg*8 .. fg*8+7
    int ng = tx >> 3;         // nodes ng*8 .. ng*8+7

    float acc[8][8];
#pragma unroll
    for (int i = 0; i < 8; i++)
#pragma unroll
        for (int j = 0; j < 8; j++) acc[i][j] = 0.f;
    float as = 0.f, ad = 0.f;   // node node0+tx

    for (int kc = 0; kc < IN_FEAT / 32; kc++) {
        __syncthreads();
        // stage X tile transposed: 128 nodes x 32 k  (1024 float4 loads)
#pragma unroll
        for (int i = tx; i < 1024; i += 128) {
            int nd = i >> 3, kq = i & 7;
            int row = node0 + nd; if (row >= N_NODES) row = N_NODES - 1;
            float4 v = ((const float4*)(x + (size_t)row * IN_FEAT + kc * 32))[kq];
            Xs[kq * 4 + 0][nd] = v.x;
            Xs[kq * 4 + 1][nd] = v.y;
            Xs[kq * 4 + 2][nd] = v.z;
            Xs[kq * 4 + 3][nd] = v.w;
        }
        // stage W chunk: 32 x 64 (512 float4)
        const float4* w4 = (const float4*)(Wsrc + kc * 32 * 64);
        float4* ws4 = (float4*)&Ws_s[0][0];
#pragma unroll
        for (int i = tx; i < 512; i += 128) ws4[i] = w4[i];
        if (tx < 32) was_s[tx] = g_wa_src[kc * 32 + tx];
        else if (tx < 64) wad_s[tx - 32] = g_wa_dst[kc * 32 + tx - 32];
        __syncthreads();

        // attention logits: thread tx handles node node0+tx
#pragma unroll
        for (int k = 0; k < 32; k++) {
            float xv = Xs[k][tx];
            as += xv * was_s[k];
            ad += xv * wad_s[k];
        }

        // 8x8 register-tiled GEMM: 2 LDS.128 X + 2 LDS.128 W per k
#pragma unroll
        for (int k = 0; k < 32; k++) {
            float4 x0 = *((const float4*)&Xs[k][ng * 8]);
            float4 x1 = *((const float4*)&Xs[k][ng * 8 + 4]);
            float xv[8] = {x0.x, x0.y, x0.z, x0.w, x1.x, x1.y, x1.z, x1.w};
            float4 w0 = ((const float4*)&Ws_s[k][0])[fg * 2 + 0];
            float4 w1 = ((const float4*)&Ws_s[k][0])[fg * 2 + 1];
            float wv[8] = {w0.x, w0.y, w0.z, w0.w, w1.x, w1.y, w1.z, w1.w};
#pragma unroll
            for (int i = 0; i < 8; i++)
#pragma unroll
                for (int j = 0; j < 8; j++) acc[i][j] += xv[i] * wv[j];
        }
    }

    int nmax = N_NODES - node0;
#pragma unroll
    for (int i = 0; i < 8; i++) {
        int nd = ng * 8 + i;
        if (nd < nmax) {
            float4* o = (float4*)(g_h_src + (size_t)(node0 + nd) * DIM_H + fg * 8);
            float4 v0 = {acc[i][0], acc[i][1], acc[i][2], acc[i][3]};
            float4 v1 = {acc[i][4], acc[i][5], acc[i][6], acc[i][7]};
            o[0] = v0; o[1] = v1;
        }
    }
    if (tx < nmax) {
        g_a_src[node0 + tx] = as;
        g_a_dst[node0 + tx] = ad;
    }
}

// ---------------------------------------------------------------------------
// eexp[i] = exp(leaky_relu(a_src[s] + a_dst[d]));  denom[d] += eexp[i]
__global__ void denom_kernel(const int* __restrict__ e32) {
    int i = blockIdx.x * blockDim.x + threadIdx.x;
    if (i >= N_EDGES) return;
    int is64 = g_is64;
    int s = load_src(e32, i, is64);
    int d = load_dst(e32, i, is64);
    float e = g_a_src[s] + g_a_dst[d];
    e = e > 0.f ? e : 0.2f * e;
    float ex = __expf(e);
    g_eexp[i] = ex;
    atomicAdd(&g_denom[d], ex);
}

// alpha[i] = eexp[i] / denom[dst[i]]  (in-place over g_eexp)
__global__ void alpha_kernel(const int* __restrict__ e32) {
    int i = blockIdx.x * blockDim.x + threadIdx.x;
    if (i >= N_EDGES) return;
    int d = load_dst(e32, i, g_is64);
    g_eexp[i] = g_eexp[i] / g_denom[d];
}

// agg[d,:] += alpha * h_src[s,:]  — 16 threads/edge, red.v4.f32
__global__ __launch_bounds__(256) void scatter_kernel(const int* __restrict__ e32) {
    int t = blockIdx.x * blockDim.x + threadIdx.x;
    int edge = t >> 4;
    int q = t & 15;
    if (edge >= N_EDGES) return;
    int is64 = g_is64;
    int s = load_src(e32, edge, is64);
    int d = load_dst(e32, edge, is64);
    float alpha = g_eexp[edge];
    float4 v = *(const float4*)(g_h_src + (size_t)s * DIM_H + q * 4);
    v.x *= alpha; v.y *= alpha; v.z *= alpha; v.w *= alpha;
    float* p = g_agg + (size_t)d * DIM_H + q * 4;
    asm volatile("red.global.add.v4.f32 [%0], {%1, %2, %3, %4};"
                 :: "l"(p), "f"(v.x), "f"(v.y), "f"(v.z), "f"(v.w)
                 : "memory");
}

// ---------------------------------------------------------------------------
// out = relu(agg + bias_conv) @ W_lin + b_lin  — 8x8 tile, 128 nodes/block
__global__ __launch_bounds__(128) void out_kernel(const float* __restrict__ Wlin,
                                                  const float* __restrict__ bias_conv,
                                                  const float* __restrict__ blin,
                                                  float* __restrict__ out) {
    __shared__ __align__(16) float Hs[32][136];
    __shared__ __align__(16) float Ws_s[32][64];
    __shared__ float bc_s[32], bl_s[64];

    int tx = threadIdx.x;
    int node0 = blockIdx.x * 128;
    int fg = tx & 7, ng = tx >> 3;

    if (tx < 64) bl_s[tx] = blin[tx];

    float acc[8][8];
#pragma unroll
    for (int i = 0; i < 8; i++)
#pragma unroll
        for (int j = 0; j < 8; j++) acc[i][j] = 0.f;

    for (int kc = 0; kc < DIM_H / 32; kc++) {
        __syncthreads();
        if (tx < 32) bc_s[tx] = bias_conv[kc * 32 + tx];
        __syncthreads();
#pragma unroll
        for (int i = tx; i < 1024; i += 128) {
            int nd = i >> 3, kq = i & 7;
            int row = node0 + nd; if (row >= N_NODES) row = N_NODES - 1;
            float4 v = ((const float4*)(g_agg + (size_t)row * DIM_H + kc * 32))[kq];
            float h0 = v.x + bc_s[kq * 4 + 0];
            float h1 = v.y + bc_s[kq * 4 + 1];
            float h2 = v.z + bc_s[kq * 4 + 2];
            float h3 = v.w + bc_s[kq * 4 + 3];
            Hs[kq * 4 + 0][nd] = h0 > 0.f ? h0 : 0.f;
            Hs[kq * 4 + 1][nd] = h1 > 0.f ? h1 : 0.f;
            Hs[kq * 4 + 2][nd] = h2 > 0.f ? h2 : 0.f;
            Hs[kq * 4 + 3][nd] = h3 > 0.f ? h3 : 0.f;
        }
        const float4* w4 = (const float4*)(Wlin + kc * 32 * 64);
        float4* ws4 = (float4*)&Ws_s[0][0];
#pragma unroll
        for (int i = tx; i < 512; i += 128) ws4[i] = w4[i];
        __syncthreads();

#pragma unroll
        for (int k = 0; k < 32; k++) {
            float4 x0 = *((const float4*)&Hs[k][ng * 8]);
            float4 x1 = *((const float4*)&Hs[k][ng * 8 + 4]);
            float hv[8] = {x0.x, x0.y, x0.z, x0.w, x1.x, x1.y, x1.z, x1.w};
            float4 w0 = ((const float4*)&Ws_s[k][0])[fg * 2 + 0];
            float4 w1 = ((const float4*)&Ws_s[k][0])[fg * 2 + 1];
            float wv[8] = {w0.x, w0.y, w0.z, w0.w, w1.x, w1.y, w1.z, w1.w};
#pragma unroll
            for (int i = 0; i < 8; i++)
#pragma unroll
                for (int j = 0; j < 8; j++) acc[i][j] += hv[i] * wv[j];
        }
    }

    int nmax = N_NODES - node0;
#pragma unroll
    for (int i = 0; i < 8; i++) {
        int nd = ng * 8 + i;
        if (nd < nmax) {
            float4* o = (float4*)(out + (size_t)(node0 + nd) * DIM_OUT + fg * 8);
            float4 v0 = {acc[i][0] + bl_s[fg * 8 + 0], acc[i][1] + bl_s[fg * 8 + 1],
                         acc[i][2] + bl_s[fg * 8 + 2], acc[i][3] + bl_s[fg * 8 + 3]};
            float4 v1 = {acc[i][4] + bl_s[fg * 8 + 4], acc[i][5] + bl_s[fg * 8 + 5],
                         acc[i][6] + bl_s[fg * 8 + 6], acc[i][7] + bl_s[fg * 8 + 7]};
            o[0] = v0; o[1] = v1;
        }
    }
}

// ---------------------------------------------------------------------------
extern "C" void kernel_launch(void* const* d_in, const int* in_sizes, int n_in,
                              void* d_out, int out_size) {
    const float* x     = (const float*)d_in[0];
    const int*   e32   = (const int*)d_in[1];
    const float* Wsrc  = (const float*)d_in[2];
    const float* Wdst  = (const float*)d_in[3];
    const float* atts  = (const float*)d_in[4];
    const float* attd  = (const float*)d_in[5];
    const float* bconv = (const float*)d_in[6];
    const float* Wlin  = (const float*)d_in[7];
    const float* blin  = (const float*)d_in[8];
    float*       out   = (float*)d_out;

    const int NODE_BLOCKS = (N_NODES + 127) / 128;   // 391

    detect_kernel<<<1, 32>>>(e32);
    init_kernel<<<512, 256>>>();
    wa_kernel<<<1, 256>>>(Wsrc, Wdst, atts, attd);
    proj_kernel<<<NODE_BLOCKS, 128>>>(x, Wsrc);
    denom_kernel<<<(N_EDGES + 255) / 256, 256>>>(e32);
    alpha_kernel<<<(N_EDGES + 255) / 256, 256>>>(e32);
    scatter_kernel<<<(N_EDGES * 16) / 256, 256>>>(e32);
    out_kernel<<<NODE_BLOCKS, 128>>>(Wlin, bconv, blin, out);
}

// round 5
// speedup vs baseline: 1.6201x; 1.0273x over previous
#include <cuda_runtime.h>

#define N_NODES 50000
#define N_EDGES 800000
#define IN_FEAT 256
#define DIM_H 64
#define DIM_OUT 64

// scratch (static device globals; no allocations allowed)
__device__ float g_h_src[N_NODES * DIM_H];   // 12.8 MB
__device__ float g_a_src[N_NODES];
__device__ float g_a_dst[N_NODES];
__device__ float g_denom[N_NODES];
__device__ float g_eexp[N_EDGES];
__device__ float g_agg[N_NODES * DIM_H];     // 12.8 MB
__device__ float g_wa_src[IN_FEAT];
__device__ float g_wa_dst[IN_FEAT];
__device__ int   g_is64;

// ---------------------------------------------------------------------------
__device__ __forceinline__ int load_src(const int* e32, int i, int is64) {
    return is64 ? e32[2 * i] : e32[i];
}
__device__ __forceinline__ int load_dst(const int* e32, int i, int is64) {
    return is64 ? e32[2 * (N_EDGES + i)] : e32[N_EDGES + i];
}

// detect edge dtype (thread 0) + wa_src/wa_dst = W@att (256 threads)
__global__ void prep_kernel(const int* __restrict__ e32,
                            const float* __restrict__ Wsrc,
                            const float* __restrict__ Wdst,
                            const float* __restrict__ atts,
                            const float* __restrict__ attd) {
    int k = threadIdx.x;
    if (k == 0) {
        const long long* e64 = (const long long*)e32;
        int ok64 = 1;
        for (int i = 0; i < 256; i++) {
            long long v = e64[i];
            if (v < 0 || v >= N_NODES) { ok64 = 0; break; }
        }
        g_is64 = ok64;
    }
    if (k < IN_FEAT) {
        float s = 0.f, d = 0.f;
#pragma unroll
        for (int j = 0; j < DIM_H; j++) {
            s += Wsrc[k * DIM_H + j] * atts[j];
            d += Wdst[k * DIM_H + j] * attd[j];
        }
        g_wa_src[k] = s;
        g_wa_dst[k] = d;
    }
}

// ---------------------------------------------------------------------------
// h_src = x @ W_src ; a_src = x @ wa_src ; a_dst = x @ wa_dst
// 128 threads, 128-node x 64-feat tile, 8x8/thread.
// Xs stride 129 (odd) -> conflict-free scalar STS/LDS.
// fg=(tx>>2)&7, ng=(tx&3)+4*(tx>>5): .128 phases see <=2 W addrs (broadcast).
__global__ __launch_bounds__(128, 4) void proj_kernel(const float* __restrict__ x,
                                                      const float* __restrict__ Wsrc) {
    __shared__ float Xs[32][129];                   // [k][node], odd stride
    __shared__ __align__(16) float Ws_s[32][64];    // [k][feat]
    __shared__ float was_s[32], wad_s[32];

    int tx = threadIdx.x;
    int node0 = blockIdx.x * 128;
    int fg = (tx >> 2) & 7;
    int ng = (tx & 3) + ((tx >> 5) << 2);

    float acc[8][8];
#pragma unroll
    for (int i = 0; i < 8; i++)
#pragma unroll
        for (int j = 0; j < 8; j++) acc[i][j] = 0.f;
    float as = 0.f, ad = 0.f;   // node node0+tx

    for (int kc = 0; kc < IN_FEAT / 32; kc++) {
        __syncthreads();
        // stage X transposed: coalesced LDG.128, conflict-free STS.32 (stride 129)
#pragma unroll
        for (int i = tx; i < 1024; i += 128) {
            int nd = i >> 3, kq = i & 7;
            int row = node0 + nd; if (row >= N_NODES) row = N_NODES - 1;
            float4 v = ((const float4*)(x + (size_t)row * IN_FEAT + kc * 32))[kq];
            Xs[kq * 4 + 0][nd] = v.x;
            Xs[kq * 4 + 1][nd] = v.y;
            Xs[kq * 4 + 2][nd] = v.z;
            Xs[kq * 4 + 3][nd] = v.w;
        }
        const float4* w4 = (const float4*)(Wsrc + kc * 32 * 64);
        float4* ws4 = (float4*)&Ws_s[0][0];
#pragma unroll
        for (int i = tx; i < 512; i += 128) ws4[i] = w4[i];
        if (tx < 32) was_s[tx] = g_wa_src[kc * 32 + tx];
        else if (tx < 64) wad_s[tx - 32] = g_wa_dst[kc * 32 + tx - 32];
        __syncthreads();

        // attention logits: thread tx <-> node node0+tx (consecutive -> cf)
#pragma unroll
        for (int k = 0; k < 32; k++) {
            float xv = Xs[k][tx];
            as += xv * was_s[k];
            ad += xv * wad_s[k];
        }

        // 8x8 register tile
#pragma unroll
        for (int k = 0; k < 32; k++) {
            float xv[8];
#pragma unroll
            for (int i = 0; i < 8; i++) xv[i] = Xs[k][ng * 8 + i];
            float4 w0 = ((const float4*)&Ws_s[k][0])[fg * 2 + 0];
            float4 w1 = ((const float4*)&Ws_s[k][0])[fg * 2 + 1];
            float wv[8] = {w0.x, w0.y, w0.z, w0.w, w1.x, w1.y, w1.z, w1.w};
#pragma unroll
            for (int i = 0; i < 8; i++)
#pragma unroll
                for (int j = 0; j < 8; j++) acc[i][j] += xv[i] * wv[j];
        }
    }

    int nmax = N_NODES - node0;
#pragma unroll
    for (int i = 0; i < 8; i++) {
        int nd = ng * 8 + i;
        if (nd < nmax) {
            float4* o = (float4*)(g_h_src + (size_t)(node0 + nd) * DIM_H + fg * 8);
            float4 v0 = {acc[i][0], acc[i][1], acc[i][2], acc[i][3]};
            float4 v1 = {acc[i][4], acc[i][5], acc[i][6], acc[i][7]};
            o[0] = v0; o[1] = v1;
        }
    }
    if (tx < nmax) {
        g_a_src[node0 + tx] = as;
        g_a_dst[node0 + tx] = ad;
    }
}

// ---------------------------------------------------------------------------
// eexp[i] = exp(leaky_relu(a_src[s]+a_dst[d]));  denom[d] += eexp[i]
__global__ void denom_kernel(const int* __restrict__ e32) {
    int i = blockIdx.x * blockDim.x + threadIdx.x;
    if (i >= N_EDGES) return;
    int is64 = g_is64;
    int s = load_src(e32, i, is64);
    int d = load_dst(e32, i, is64);
    float e = g_a_src[s] + g_a_dst[d];
    e = e > 0.f ? e : 0.2f * e;
    float ex = __expf(e);
    g_eexp[i] = ex;
    atomicAdd(&g_denom[d], ex);
}

// agg[d,:] += (eexp/denom[d]) * h_src[s,:]  — 16 lanes/edge, alpha via shfl,
// red.global.add.v4.f32 (no return). Grid sized exactly: no inactive lanes.
__global__ __launch_bounds__(256) void scatter_kernel(const int* __restrict__ e32) {
    int t = blockIdx.x * blockDim.x + threadIdx.x;
    int edge = t >> 4;
    int q = t & 15;
    int lane = threadIdx.x & 31;
    int is64 = g_is64;
    int s = load_src(e32, edge, is64);
    int d = load_dst(e32, edge, is64);
    float alpha = 0.f;
    if ((lane & 15) == 0) alpha = g_eexp[edge] / g_denom[d];
    alpha = __shfl_sync(0xFFFFFFFFu, alpha, lane & 16);
    float4 v = *(const float4*)(g_h_src + (size_t)s * DIM_H + q * 4);
    v.x *= alpha; v.y *= alpha; v.z *= alpha; v.w *= alpha;
    float* p = g_agg + (size_t)d * DIM_H + q * 4;
    asm volatile("red.global.add.v4.f32 [%0], {%1, %2, %3, %4};"
                 :: "l"(p), "f"(v.x), "f"(v.y), "f"(v.z), "f"(v.w)
                 : "memory");
}

// ---------------------------------------------------------------------------
// out = relu(agg + bias_conv) @ W_lin + b_lin — same layout tricks, K=64
__global__ __launch_bounds__(128, 4) void out_kernel(const float* __restrict__ Wlin,
                                                     const float* __restrict__ bias_conv,
                                                     const float* __restrict__ blin,
                                                     float* __restrict__ out) {
    __shared__ float Hs[32][129];
    __shared__ __align__(16) float Ws_s[32][64];
    __shared__ float bc_s[32], bl_s[64];

    int tx = threadIdx.x;
    int node0 = blockIdx.x * 128;
    int fg = (tx >> 2) & 7;
    int ng = (tx & 3) + ((tx >> 5) << 2);

    if (tx < 64) bl_s[tx] = blin[tx];

    float acc[8][8];
#pragma unroll
    for (int i = 0; i < 8; i++)
#pragma unroll
        for (int j = 0; j < 8; j++) acc[i][j] = 0.f;

    for (int kc = 0; kc < DIM_H / 32; kc++) {
        __syncthreads();
        if (tx < 32) bc_s[tx] = bias_conv[kc * 32 + tx];
        __syncthreads();
#pragma unroll
        for (int i = tx; i < 1024; i += 128) {
            int nd = i >> 3, kq = i & 7;
            int row = node0 + nd; if (row >= N_NODES) row = N_NODES - 1;
            float4 v = ((const float4*)(g_agg + (size_t)row * DIM_H + kc * 32))[kq];
            float h0 = v.x + bc_s[kq * 4 + 0];
            float h1 = v.y + bc_s[kq * 4 + 1];
            float h2 = v.z + bc_s[kq * 4 + 2];
            float h3 = v.w + bc_s[kq * 4 + 3];
            Hs[kq * 4 + 0][nd] = h0 > 0.f ? h0 : 0.f;
            Hs[kq * 4 + 1][nd] = h1 > 0.f ? h1 : 0.f;
            Hs[kq * 4 + 2][nd] = h2 > 0.f ? h2 : 0.f;
            Hs[kq * 4 + 3][nd] = h3 > 0.f ? h3 : 0.f;
        }
        const float4* w4 = (const float4*)(Wlin + kc * 32 * 64);
        float4* ws4 = (float4*)&Ws_s[0][0];
#pragma unroll
        for (int i = tx; i < 512; i += 128) ws4[i] = w4[i];
        __syncthreads();

#pragma unroll
        for (int k = 0; k < 32; k++) {
            float hv[8];
#pragma unroll
            for (int i = 0; i < 8; i++) hv[i] = Hs[k][ng * 8 + i];
            float4 w0 = ((const float4*)&Ws_s[k][0])[fg * 2 + 0];
            float4 w1 = ((const float4*)&Ws_s[k][0])[fg * 2 + 1];
            float wv[8] = {w0.x, w0.y, w0.z, w0.w, w1.x, w1.y, w1.z, w1.w};
#pragma unroll
            for (int i = 0; i < 8; i++)
#pragma unroll
                for (int j = 0; j < 8; j++) acc[i][j] += hv[i] * wv[j];
        }
    }

    int nmax = N_NODES - node0;
#pragma unroll
    for (int i = 0; i < 8; i++) {
        int nd = ng * 8 + i;
        if (nd < nmax) {
            float4* o = (float4*)(out + (size_t)(node0 + nd) * DIM_OUT + fg * 8);
            float4 v0 = {acc[i][0] + bl_s[fg * 8 + 0], acc[i][1] + bl_s[fg * 8 + 1],
                         acc[i][2] + bl_s[fg * 8 + 2], acc[i][3] + bl_s[fg * 8 + 3]};
            float4 v1 = {acc[i][4] + bl_s[fg * 8 + 4], acc[i][5] + bl_s[fg * 8 + 5],
                         acc[i][6] + bl_s[fg * 8 + 6], acc[i][7] + bl_s[fg * 8 + 7]};
            o[0] = v0; o[1] = v1;
        }
    }
}

// ---------------------------------------------------------------------------
extern "C" void kernel_launch(void* const* d_in, const int* in_sizes, int n_in,
                              void* d_out, int out_size) {
    const float* x     = (const float*)d_in[0];
    const int*   e32   = (const int*)d_in[1];
    const float* Wsrc  = (const float*)d_in[2];
    const float* Wdst  = (const float*)d_in[3];
    const float* atts  = (const float*)d_in[4];
    const float* attd  = (const float*)d_in[5];
    const float* bconv = (const float*)d_in[6];
    const float* Wlin  = (const float*)d_in[7];
    const float* blin  = (const float*)d_in[8];
    float*       out   = (float*)d_out;

    void* agg_ptr = nullptr;
    void* den_ptr = nullptr;
    cudaGetSymbolAddress(&agg_ptr, g_agg);
    cudaGetSymbolAddress(&den_ptr, g_denom);
    cudaMemsetAsync(agg_ptr, 0, (size_t)N_NODES * DIM_H * sizeof(float), 0);
    cudaMemsetAsync(den_ptr, 0, (size_t)N_NODES * sizeof(float), 0);

    const int NODE_BLOCKS = (N_NODES + 127) / 128;   // 391

    prep_kernel<<<1, 256>>>(e32, Wsrc, Wdst, atts, attd);
    proj_kernel<<<NODE_BLOCKS, 128>>>(x, Wsrc);
    denom_kernel<<<(N_EDGES + 255) / 256, 256>>>(e32);
    scatter_kernel<<<(N_EDGES * 16) / 256, 256>>>(e32);   // exact: 50000 blocks
    out_kernel<<<NODE_BLOCKS, 128>>>(Wlin, bconv, blin, out);
}